// round 16
// baseline (speedup 1.0000x reference)
#include <cuda_runtime.h>
#include <cuda_bf16.h>

#define NNODE 50000
#define EDGES 600000
#define NGRAPH 500
#define NPG 100
#define KSEL 30
#define FIN 128
#define D 64
#define DT 129
#define SLOT 64

typedef unsigned long long u64;

__device__ __forceinline__ u64 dup2(float v) {
    u64 r;
    asm("mov.b64 %0, {%1, %1};" : "=l"(r) : "r"(__float_as_uint(v)));
    return r;
}
__device__ __forceinline__ void fma2(u64& acc, u64 a, u64 b) {
    asm("fma.rn.f32x2 %0, %1, %2, %0;" : "+l"(acc) : "l"(a), "l"(b));
}
__device__ __forceinline__ void add2(u64& acc, u64 v) {
    asm("add.rn.f32x2 %0, %1, %0;" : "+l"(acc) : "l"(v));
}

// ---------------- scratch ----------------
__device__ int    g_cnt[NNODE];           // zero at call start; k_s3 restores zero
__device__ int    g_slot[NNODE * SLOT];
__device__ float  g_H[NNODE * D];
__device__ float  g_h[NNODE * D];         // h1
__device__ float  g_h2[NNODE * D];        // h2
__device__ float4 g_dots[NNODE];          // .x = s0a, .y = s0b, .z = u
__device__ float  g_s1v[NNODE];
__device__ float  g_s2v[NNODE];
__device__ float  g_h3[NNODE];
__device__ float  g_h3s[NNODE];
__device__ float  g_x3[NNODE];

// ---------------- setup ----------------
__global__ void k_fillslots(const int* __restrict__ ei) {
    int e = blockIdx.x * blockDim.x + threadIdx.x;
    if (e >= EDGES) return;
    int s = ei[e];
    int d = ei[EDGES + e];
    int p = atomicAdd(&g_cnt[d], 1);
    g_slot[d * SLOT + p] = s;
}

// ---------------- SGEMM (round-10 form): BM=128, BN=64, BK=16, 256 thr, 4x8 tile ----------------
template <int K>
__global__ void __launch_bounds__(256, 3) k_gemm(const float* __restrict__ X,
                                                 const float* __restrict__ W,
                                                 float* __restrict__ out) {
    __shared__ float Xt[16][132];
    __shared__ float Wsm[16][64];
    int tid = threadIdx.x;
    int rb = blockIdx.x * 128;
    int tx = tid & 7;
    int ty = tid >> 3;
    int fr0 = tid >> 2;
    int fk0 = tid & 3;
    int fr1 = (tid + 256) >> 2;
    int fk1 = (tid + 256) & 3;
    int wkk = tid >> 4, wc4 = tid & 15;

    u64 acc2[4][4];
#pragma unroll
    for (int r = 0; r < 4; r++)
#pragma unroll
        for (int c = 0; c < 4; c++) acc2[r][c] = 0ULL;

    float4 xA, xB, wv;
    {
        int grA = rb + fr0, grB = rb + fr1;
        xA = (grA < NNODE) ? *(const float4*)(X + (size_t)grA * K + fk0 * 4)
                           : make_float4(0.f, 0.f, 0.f, 0.f);
        xB = (grB < NNODE) ? *(const float4*)(X + (size_t)grB * K + fk1 * 4)
                           : make_float4(0.f, 0.f, 0.f, 0.f);
        wv = *(const float4*)(W + (size_t)wkk * 64 + wc4 * 4);
    }
#pragma unroll 1
    for (int k0 = 0; k0 < K; k0 += 16) {
        Xt[fk0 * 4 + 0][fr0] = xA.x; Xt[fk0 * 4 + 1][fr0] = xA.y;
        Xt[fk0 * 4 + 2][fr0] = xA.z; Xt[fk0 * 4 + 3][fr0] = xA.w;
        Xt[fk1 * 4 + 0][fr1] = xB.x; Xt[fk1 * 4 + 1][fr1] = xB.y;
        Xt[fk1 * 4 + 2][fr1] = xB.z; Xt[fk1 * 4 + 3][fr1] = xB.w;
        *(float4*)&Wsm[wkk][wc4 * 4] = wv;
        __syncthreads();
        if (k0 + 16 < K) {
            int grA = rb + fr0, grB = rb + fr1;
            xA = (grA < NNODE) ? *(const float4*)(X + (size_t)grA * K + k0 + 16 + fk0 * 4)
                               : make_float4(0.f, 0.f, 0.f, 0.f);
            xB = (grB < NNODE) ? *(const float4*)(X + (size_t)grB * K + k0 + 16 + fk1 * 4)
                               : make_float4(0.f, 0.f, 0.f, 0.f);
            wv = *(const float4*)(W + (size_t)(k0 + 16 + wkk) * 64 + wc4 * 4);
        }
#pragma unroll
        for (int kk = 0; kk < 16; kk++) {
            float a[4];
            *(float4*)&a[0] = *(const float4*)&Xt[kk][ty * 4];
            u64 b2[4];
            const u64* bp = (const u64*)&Wsm[kk][tx * 8];
            b2[0] = bp[0]; b2[1] = bp[1]; b2[2] = bp[2]; b2[3] = bp[3];
#pragma unroll
            for (int r = 0; r < 4; r++) {
                u64 ar = dup2(a[r]);
#pragma unroll
                for (int c = 0; c < 4; c++) fma2(acc2[r][c], ar, b2[c]);
            }
        }
        __syncthreads();
    }
#pragma unroll
    for (int r = 0; r < 4; r++) {
        int gr = rb + ty * 4 + r;
        if (gr < NNODE) {
            float sc = rsqrtf((float)g_cnt[gr] + 1.0f);
            float2 p0 = *(float2*)&acc2[r][0];
            float2 p1 = *(float2*)&acc2[r][1];
            float2 p2 = *(float2*)&acc2[r][2];
            float2 p3 = *(float2*)&acc2[r][3];
            float4* op = (float4*)(out + (size_t)gr * 64 + tx * 8);
            op[0] = make_float4(p0.x * sc, p0.y * sc, p1.x * sc, p1.y * sc);
            op[1] = make_float4(p2.x * sc, p2.y * sc, p3.x * sc, p3.y * sc);
        }
    }
}

// ---------------- 64-wide aggregation: TWO warps per node + fused dots ----------------
// Warp pair splits the neighbor list by 4-batches; warp1 deposits partial in smem.
__global__ void __launch_bounds__(256) k_agg64f(const float* __restrict__ Hin,
                                                const float* __restrict__ bias,
                                                const float* __restrict__ Wg,
                                                const float* __restrict__ Wu,
                                                float* __restrict__ out, int doff) {
    __shared__ float2 part[4][32];
    int tid = threadIdx.x;
    int node = (blockIdx.x * 256 + tid) >> 6;   // 4 nodes per block; 50000 = 12500*4 exact
    int lane = tid & 31;
    int pair = (tid >> 5) & 1;
    int slot = tid >> 6;                         // 0..3
    int cnt = g_cnt[node];
    const u64* Hu = (const u64*)Hin;
    u64 acc = 0ULL;
    if (pair == 0) acc = __ldg(&Hu[node * 32 + lane]);
    const int* sl = g_slot + (size_t)node * SLOT;
    for (int b = pair; b * 4 < cnt; b += 2) {
        int j0 = b * 4;
        int rem = cnt - j0;
        if (rem >= 4) {
            int4 ss = __ldg((const int4*)(sl + j0));
            u64 v0 = __ldg(&Hu[ss.x * 32 + lane]);
            u64 v1 = __ldg(&Hu[ss.y * 32 + lane]);
            u64 v2 = __ldg(&Hu[ss.z * 32 + lane]);
            u64 v3 = __ldg(&Hu[ss.w * 32 + lane]);
            add2(acc, v0); add2(acc, v1); add2(acc, v2); add2(acc, v3);
        } else {
            for (int t = 0; t < rem; t++) {
                int s = __ldg(&sl[j0 + t]);
                u64 v = __ldg(&Hu[s * 32 + lane]);
                add2(acc, v);
            }
        }
    }
    if (pair == 1) part[slot][lane] = *(float2*)&acc;
    __syncthreads();
    if (pair == 1) return;
    float2 pv = part[slot][lane];
    float2 av = *(float2*)&acc;
    av.x += pv.x;
    av.y += pv.y;
    float di = rsqrtf((float)cnt + 1.0f);
    float2 bv = ((const float2*)bias)[lane];
    float ax = fmaxf(fmaf(av.x, di, bv.x), 0.f);
    float ay = fmaxf(fmaf(av.y, di, bv.y), 0.f);
    ((float2*)out)[node * 32 + lane] = make_float2(ax, ay);
    float* dots = (float*)g_dots;
    float2 wg = ((const float2*)Wg)[lane];
    float dg = ax * wg.x + ay * wg.y;
#pragma unroll
    for (int o = 16; o; o >>= 1) dg += __shfl_xor_sync(0xffffffffu, dg, o);
    if (lane == 0) dots[node * 4 + doff] = dg * di;
    if (Wu) {
        float2 wu = ((const float2*)Wu)[lane];
        float du = ax * wu.x + ay * wu.y;
#pragma unroll
        for (int o = 16; o; o >>= 1) du += __shfl_xor_sync(0xffffffffu, du, o);
        if (lane == 0) dots[node * 4 + doff + 1] = du * di;
    }
}

// ---------------- fused scalar gates: s1v, s2v, h3 (float4 gathers) ----------------
__global__ void k_sgates(const float* __restrict__ bs1, const float* __restrict__ bs2,
                         const float* __restrict__ b3) {
    int gt = blockIdx.x * blockDim.x + threadIdx.x;
    int i = gt >> 3;
    int sub = threadIdx.x & 7;
    if (i >= NNODE) return;
    int cnt = g_cnt[i];
    float di = rsqrtf((float)cnt + 1.0f);
    float accA = 0.f, accB = 0.f, accU = 0.f;
    if (sub == 0) {
        float4 v = __ldg(&g_dots[i]);
        accA = v.x; accB = v.y; accU = v.z;
    }
    const int* sl = g_slot + (size_t)i * SLOT;
    for (int j = sub; j < cnt; j += 8) {
        int s = __ldg(&sl[j]);
        float4 v = __ldg(&g_dots[s]);
        accA += v.x;
        accB += v.y;
        accU += v.z;
    }
#pragma unroll
    for (int o = 4; o; o >>= 1) {
        accA += __shfl_xor_sync(0xffffffffu, accA, o);
        accB += __shfl_xor_sync(0xffffffffu, accB, o);
        accU += __shfl_xor_sync(0xffffffffu, accU, o);
    }
    if (sub == 0) {
        g_s1v[i] = fmaf(accA, di, bs1[0]);
        g_s2v[i] = fmaf(accB, di, bs2[0]);
        float h3 = fmaxf(fmaf(accU, di, b3[0]), 0.f);
        g_h3[i] = h3;
        g_h3s[i] = h3 * di;
    }
}

// ---------------- s3/x3 ; restores g_cnt=0 ----------------
__global__ void k_s3(const float* __restrict__ Ws3, const float* __restrict__ bs3) {
    int gt = blockIdx.x * blockDim.x + threadIdx.x;
    int i = gt >> 3;
    int sub = threadIdx.x & 7;
    if (i >= NNODE) return;
    int cnt = g_cnt[i];
    float di = rsqrtf((float)cnt + 1.0f);
    float acc = (sub == 0) ? g_h3s[i] : 0.f;
    const int* sl = g_slot + (size_t)i * SLOT;
    for (int j = sub; j < cnt; j += 8) {
        int s = __ldg(&sl[j]);
        acc += g_h3s[s];
    }
#pragma unroll
    for (int o = 4; o; o >>= 1) acc += __shfl_xor_sync(0xffffffffu, acc, o);
    if (sub == 0) {
        g_x3[i] = fmaf(acc * di, Ws3[0], bs3[0]) * g_h3[i];
        g_cnt[i] = 0;
    }
}

// ---------------- fused sort-pool + conv head ----------------
__global__ void __launch_bounds__(128) k_head(
    const float* __restrict__ Wc1, const float* __restrict__ bc1,
    const float* __restrict__ Wc2, const float* __restrict__ bc2,
    const float* __restrict__ Wl1, const float* __restrict__ bl1,
    const float* __restrict__ Wl2, const float* __restrict__ bl2,
    float* __restrict__ out) {
    __shared__ float x3s[NPG];
    __shared__ unsigned long long keys[NPG];
    __shared__ int sel[KSEL];
    __shared__ float pooled[KSEL * DT];
    __shared__ float c1s[16 * 30];
    __shared__ float mps[16 * 15];
    __shared__ float flat[32 * 11];
    __shared__ float red[128];
    int g = blockIdx.x, tid = threadIdx.x;
    int base = g * NPG;

    for (int i = tid; i < NPG; i += 128) x3s[i] = g_x3[base + i];
    __syncthreads();
    for (int i = tid; i < NPG; i += 128) {
        unsigned u = __float_as_uint(-x3s[i]);
        u = (u & 0x80000000u) ? ~u : (u | 0x80000000u);
        keys[i] = ((unsigned long long)u << 32) | (unsigned)i;
    }
    __syncthreads();
    if (tid < NPG) {
        unsigned long long ki = keys[tid];
        int c = 0;
        for (int j = 0; j < NPG; j++) c += (keys[j] < ki) ? 1 : 0;
        if (c < KSEL) sel[c] = tid;
    }
    __syncthreads();
    for (int idx = tid; idx < KSEL * DT; idx += 128) {
        int r = idx / DT, d = idx - r * DT;
        int ln = sel[r];
        int node = base + ln;
        float v;
        if (d < 64) v = g_s1v[node] * g_h[node * 64 + d];
        else if (d < 128) v = g_s2v[node] * g_h2[node * 64 + d - 64];
        else v = x3s[ln];
        pooled[idx] = v;
    }
    __syncthreads();
    for (int idx = tid; idx < 16 * 30; idx += 128) {
        int o = idx / 30, k = idx - o * 30;
        float acc = bc1[o];
        const float* w = Wc1 + o * DT;
        for (int d = 0; d < DT; d++) acc += pooled[k * DT + d] * w[d];
        c1s[o * 30 + k] = fmaxf(acc, 0.f);
    }
    __syncthreads();
    for (int idx = tid; idx < 16 * 15; idx += 128) {
        int o = idx / 15, p = idx - o * 15;
        mps[idx] = fmaxf(c1s[o * 30 + 2 * p], c1s[o * 30 + 2 * p + 1]);
    }
    __syncthreads();
    for (int idx = tid; idx < 32 * 11; idx += 128) {
        int o = idx / 11, p = idx - o * 11;
        float acc = bc2[o];
        for (int i2 = 0; i2 < 16; i2++) {
            const float* w = Wc2 + (o * 16 + i2) * 5;
#pragma unroll
            for (int t = 0; t < 5; t++) acc += mps[i2 * 15 + p + t] * w[t];
        }
        flat[idx] = fmaxf(acc, 0.f);
    }
    __syncthreads();
    {
        int w = tid >> 5, lane = tid & 31;
        float fl[11];
#pragma unroll
        for (int it = 0; it < 11; it++) fl[it] = flat[lane + it * 32];
        for (int jj = 0; jj < 32; jj++) {
            int j = w * 32 + jj;
            const float* wr = Wl1 + j * 352;
            float acc = 0.f;
#pragma unroll
            for (int it = 0; it < 11; it++) acc += fl[it] * wr[lane + it * 32];
#pragma unroll
            for (int o = 16; o; o >>= 1) acc += __shfl_xor_sync(0xffffffffu, acc, o);
            if (lane == 0) {
                float hv = fmaxf(acc + bl1[j], 0.f);
                red[j] = hv * Wl2[j];
            }
        }
    }
    __syncthreads();
    for (int off = 64; off; off >>= 1) {
        if (tid < off) red[tid] += red[tid + off];
        __syncthreads();
    }
    if (tid == 0) out[g] = red[0] + bl2[0];
}

// ---------------- launcher ----------------
extern "C" void kernel_launch(void* const* d_in, const int* in_sizes, int n_in,
                              void* d_out, int out_size) {
    const float* x   = (const float*)d_in[0];
    const int*   ei  = (const int*)  d_in[1];
    const float* W1  = (const float*)d_in[2];
    const float* b1  = (const float*)d_in[3];
    const float* W2  = (const float*)d_in[4];
    const float* b2  = (const float*)d_in[5];
    const float* W3  = (const float*)d_in[6];
    const float* b3  = (const float*)d_in[7];
    const float* Ws1 = (const float*)d_in[8];
    const float* bs1 = (const float*)d_in[9];
    const float* Ws2 = (const float*)d_in[10];
    const float* bs2 = (const float*)d_in[11];
    const float* Ws3 = (const float*)d_in[12];
    const float* bs3 = (const float*)d_in[13];
    const float* Wc1 = (const float*)d_in[14];
    const float* bc1 = (const float*)d_in[15];
    const float* Wc2 = (const float*)d_in[16];
    const float* bc2 = (const float*)d_in[17];
    const float* Wl1 = (const float*)d_in[18];
    const float* bl1 = (const float*)d_in[19];
    const float* Wl2 = (const float*)d_in[20];
    const float* bl2 = (const float*)d_in[21];
    float* out = (float*)d_out;

    float *dH, *dh, *dh2;
    cudaGetSymbolAddress((void**)&dH,  g_H);
    cudaGetSymbolAddress((void**)&dh,  g_h);
    cudaGetSymbolAddress((void**)&dh2, g_h2);

    const int TB = 256;
    int gE  = (EDGES + TB - 1) / TB;
    int gW2 = (NNODE * 64) / TB;     // two warps per node (exact: 12500)
    int gW8 = (NNODE * 8 + TB - 1) / TB;

    // 0: structure
    k_fillslots<<<gE, TB>>>(ei);
    // 1: gemm128
    k_gemm<FIN><<<(NNODE + 127) / 128, 256>>>(x, W1, dH);
    // 2: agg64f #1 -> h1, dots.x
    k_agg64f<<<gW2, TB>>>(dH, b1, Ws1, nullptr, dh, 0);
    // 3: gemm64 (h1 -> H2)   <-- profiled slot
    k_gemm<D><<<(NNODE + 127) / 128, 256>>>(dh, W2, dH);
    // 4: agg64f #2 -> h2, dots.y, dots.z
    k_agg64f<<<gW2, TB>>>(dH, b2, Ws2, W3, dh2, 1);
    // 5: fused scalar gates -> s1v, s2v, h3
    k_sgates<<<gW8, TB>>>(bs1, bs2, b3);
    // 6: s3/x3 (+ cnt reset)
    k_s3<<<gW8, TB>>>(Ws3, bs3);
    // 7: head
    k_head<<<NGRAPH, 128>>>(Wc1, bc1, Wc2, bc2, Wl1, bl1, Wl2, bl2, out);

    (void)in_sizes; (void)n_in; (void)out_size;
}

// round 17
// speedup vs baseline: 1.6482x; 1.6482x over previous
#include <cuda_runtime.h>
#include <cuda_bf16.h>

#define NNODE 50000
#define EDGES 600000
#define NGRAPH 500
#define NPG 100
#define KSEL 30
#define FIN 128
#define D 64
#define DT 129
#define SLOT 64

typedef unsigned long long u64;

__device__ __forceinline__ u64 dup2(float v) {
    u64 r;
    asm("mov.b64 %0, {%1, %1};" : "=l"(r) : "r"(__float_as_uint(v)));
    return r;
}
__device__ __forceinline__ void fma2(u64& acc, u64 a, u64 b) {
    asm("fma.rn.f32x2 %0, %1, %2, %0;" : "+l"(acc) : "l"(a), "l"(b));
}
__device__ __forceinline__ void add2(u64& acc, u64 v) {
    asm("add.rn.f32x2 %0, %1, %0;" : "+l"(acc) : "l"(v));
}

// ---------------- scratch ----------------
__device__ int    g_cnt[NNODE];           // zero at call start; k_s3 restores zero
__device__ int    g_slot[NNODE * SLOT];
__device__ float  g_H[NNODE * D];
__device__ float  g_h[NNODE * D];         // h1
__device__ float  g_h2[NNODE * D];        // h2
__device__ float4 g_dots[NNODE];          // .x = s0a, .y = s0b, .z = u
__device__ float  g_s1v[NNODE];
__device__ float  g_s2v[NNODE];
__device__ float  g_h3[NNODE];
__device__ float  g_h3s[NNODE];
__device__ float  g_x3[NNODE];

// ---------------- setup ----------------
__global__ void k_fillslots(const int* __restrict__ ei) {
    int e = blockIdx.x * blockDim.x + threadIdx.x;
    if (e >= EDGES) return;
    int s = ei[e];
    int d = ei[EDGES + e];
    int p = atomicAdd(&g_cnt[d], 1);
    g_slot[d * SLOT + p] = s;
}

// ---------------- SGEMM (round-10 form): BM=128, BN=64, BK=16, 256 thr, 4x8 tile ----------------
template <int K>
__global__ void __launch_bounds__(256, 3) k_gemm(const float* __restrict__ X,
                                                 const float* __restrict__ W,
                                                 float* __restrict__ out) {
    __shared__ float Xt[16][132];
    __shared__ float Wsm[16][64];
    int tid = threadIdx.x;
    int rb = blockIdx.x * 128;
    int tx = tid & 7;
    int ty = tid >> 3;
    int fr0 = tid >> 2;
    int fk0 = tid & 3;
    int fr1 = (tid + 256) >> 2;
    int fk1 = (tid + 256) & 3;
    int wkk = tid >> 4, wc4 = tid & 15;

    u64 acc2[4][4];
#pragma unroll
    for (int r = 0; r < 4; r++)
#pragma unroll
        for (int c = 0; c < 4; c++) acc2[r][c] = 0ULL;

    float4 xA, xB, wv;
    {
        int grA = rb + fr0, grB = rb + fr1;
        xA = (grA < NNODE) ? *(const float4*)(X + (size_t)grA * K + fk0 * 4)
                           : make_float4(0.f, 0.f, 0.f, 0.f);
        xB = (grB < NNODE) ? *(const float4*)(X + (size_t)grB * K + fk1 * 4)
                           : make_float4(0.f, 0.f, 0.f, 0.f);
        wv = *(const float4*)(W + (size_t)wkk * 64 + wc4 * 4);
    }
#pragma unroll 1
    for (int k0 = 0; k0 < K; k0 += 16) {
        Xt[fk0 * 4 + 0][fr0] = xA.x; Xt[fk0 * 4 + 1][fr0] = xA.y;
        Xt[fk0 * 4 + 2][fr0] = xA.z; Xt[fk0 * 4 + 3][fr0] = xA.w;
        Xt[fk1 * 4 + 0][fr1] = xB.x; Xt[fk1 * 4 + 1][fr1] = xB.y;
        Xt[fk1 * 4 + 2][fr1] = xB.z; Xt[fk1 * 4 + 3][fr1] = xB.w;
        *(float4*)&Wsm[wkk][wc4 * 4] = wv;
        __syncthreads();
        if (k0 + 16 < K) {
            int grA = rb + fr0, grB = rb + fr1;
            xA = (grA < NNODE) ? *(const float4*)(X + (size_t)grA * K + k0 + 16 + fk0 * 4)
                               : make_float4(0.f, 0.f, 0.f, 0.f);
            xB = (grB < NNODE) ? *(const float4*)(X + (size_t)grB * K + k0 + 16 + fk1 * 4)
                               : make_float4(0.f, 0.f, 0.f, 0.f);
            wv = *(const float4*)(W + (size_t)(k0 + 16 + wkk) * 64 + wc4 * 4);
        }
#pragma unroll
        for (int kk = 0; kk < 16; kk++) {
            float a[4];
            *(float4*)&a[0] = *(const float4*)&Xt[kk][ty * 4];
            u64 b2[4];
            const u64* bp = (const u64*)&Wsm[kk][tx * 8];
            b2[0] = bp[0]; b2[1] = bp[1]; b2[2] = bp[2]; b2[3] = bp[3];
#pragma unroll
            for (int r = 0; r < 4; r++) {
                u64 ar = dup2(a[r]);
#pragma unroll
                for (int c = 0; c < 4; c++) fma2(acc2[r][c], ar, b2[c]);
            }
        }
        __syncthreads();
    }
#pragma unroll
    for (int r = 0; r < 4; r++) {
        int gr = rb + ty * 4 + r;
        if (gr < NNODE) {
            float sc = rsqrtf((float)g_cnt[gr] + 1.0f);
            float2 p0 = *(float2*)&acc2[r][0];
            float2 p1 = *(float2*)&acc2[r][1];
            float2 p2 = *(float2*)&acc2[r][2];
            float2 p3 = *(float2*)&acc2[r][3];
            float4* op = (float4*)(out + (size_t)gr * 64 + tx * 8);
            op[0] = make_float4(p0.x * sc, p0.y * sc, p1.x * sc, p1.y * sc);
            op[1] = make_float4(p2.x * sc, p2.y * sc, p3.x * sc, p3.y * sc);
        }
    }
}

// ---------------- 64-wide aggregation (warp-per-node, 8-deep) + fused dots ----------------
template <bool HAS_WU>
__global__ void k_agg64f(const float* __restrict__ Hin, const float* __restrict__ bias,
                         const float* __restrict__ Wg, const float* __restrict__ Wu,
                         float* __restrict__ out, int doff) {
    int warp = (blockIdx.x * blockDim.x + threadIdx.x) >> 5;
    int lane = threadIdx.x & 31;
    if (warp >= NNODE) return;
    int i = warp;
    int cnt = g_cnt[i];
    float di = rsqrtf((float)cnt + 1.0f);
    const u64* Hu = (const u64*)Hin;
    u64 acc = __ldg(&Hu[i * 32 + lane]);
    const int* sl = g_slot + (size_t)i * SLOT;
    int j = 0;
    for (; j + 8 <= cnt; j += 8) {
        int4 sa = __ldg((const int4*)(sl + j));
        int4 sb = __ldg((const int4*)(sl + j + 4));
        u64 v0 = __ldg(&Hu[sa.x * 32 + lane]);
        u64 v1 = __ldg(&Hu[sa.y * 32 + lane]);
        u64 v2 = __ldg(&Hu[sa.z * 32 + lane]);
        u64 v3 = __ldg(&Hu[sa.w * 32 + lane]);
        u64 v4 = __ldg(&Hu[sb.x * 32 + lane]);
        u64 v5 = __ldg(&Hu[sb.y * 32 + lane]);
        u64 v6 = __ldg(&Hu[sb.z * 32 + lane]);
        u64 v7 = __ldg(&Hu[sb.w * 32 + lane]);
        add2(acc, v0); add2(acc, v1); add2(acc, v2); add2(acc, v3);
        add2(acc, v4); add2(acc, v5); add2(acc, v6); add2(acc, v7);
    }
    if (j + 4 <= cnt) {
        int4 ss = __ldg((const int4*)(sl + j));
        u64 v0 = __ldg(&Hu[ss.x * 32 + lane]);
        u64 v1 = __ldg(&Hu[ss.y * 32 + lane]);
        u64 v2 = __ldg(&Hu[ss.z * 32 + lane]);
        u64 v3 = __ldg(&Hu[ss.w * 32 + lane]);
        add2(acc, v0); add2(acc, v1); add2(acc, v2); add2(acc, v3);
        j += 4;
    }
    for (; j < cnt; j++) {
        int s = __ldg(&sl[j]);
        u64 v = __ldg(&Hu[s * 32 + lane]);
        add2(acc, v);
    }
    float2 av = *(float2*)&acc;
    float2 bv = ((const float2*)bias)[lane];
    float ax = fmaxf(fmaf(av.x, di, bv.x), 0.f);
    float ay = fmaxf(fmaf(av.y, di, bv.y), 0.f);
    ((float2*)out)[i * 32 + lane] = make_float2(ax, ay);
    float* dots = (float*)g_dots;
    float2 wg = ((const float2*)Wg)[lane];
    float dg = ax * wg.x + ay * wg.y;
#pragma unroll
    for (int o = 16; o; o >>= 1) dg += __shfl_xor_sync(0xffffffffu, dg, o);
    if (lane == 0) dots[i * 4 + doff] = dg * di;
    if (HAS_WU) {
        float2 wu = ((const float2*)Wu)[lane];
        float du = ax * wu.x + ay * wu.y;
#pragma unroll
        for (int o = 16; o; o >>= 1) du += __shfl_xor_sync(0xffffffffu, du, o);
        if (lane == 0) dots[i * 4 + doff + 1] = du * di;
    }
}

// ---------------- fused scalar gates: s1v, s2v, h3 (float4 gathers) ----------------
__global__ void k_sgates(const float* __restrict__ bs1, const float* __restrict__ bs2,
                         const float* __restrict__ b3) {
    int gt = blockIdx.x * blockDim.x + threadIdx.x;
    int i = gt >> 3;
    int sub = threadIdx.x & 7;
    if (i >= NNODE) return;
    int cnt = g_cnt[i];
    float di = rsqrtf((float)cnt + 1.0f);
    float accA = 0.f, accB = 0.f, accU = 0.f;
    if (sub == 0) {
        float4 v = __ldg(&g_dots[i]);
        accA = v.x; accB = v.y; accU = v.z;
    }
    const int* sl = g_slot + (size_t)i * SLOT;
    for (int j = sub; j < cnt; j += 8) {
        int s = __ldg(&sl[j]);
        float4 v = __ldg(&g_dots[s]);
        accA += v.x;
        accB += v.y;
        accU += v.z;
    }
#pragma unroll
    for (int o = 4; o; o >>= 1) {
        accA += __shfl_xor_sync(0xffffffffu, accA, o);
        accB += __shfl_xor_sync(0xffffffffu, accB, o);
        accU += __shfl_xor_sync(0xffffffffu, accU, o);
    }
    if (sub == 0) {
        g_s1v[i] = fmaf(accA, di, bs1[0]);
        g_s2v[i] = fmaf(accB, di, bs2[0]);
        float h3 = fmaxf(fmaf(accU, di, b3[0]), 0.f);
        g_h3[i] = h3;
        g_h3s[i] = h3 * di;
    }
}

// ---------------- s3/x3 ; restores g_cnt=0 ----------------
__global__ void k_s3(const float* __restrict__ Ws3, const float* __restrict__ bs3) {
    int gt = blockIdx.x * blockDim.x + threadIdx.x;
    int i = gt >> 3;
    int sub = threadIdx.x & 7;
    if (i >= NNODE) return;
    int cnt = g_cnt[i];
    float di = rsqrtf((float)cnt + 1.0f);
    float acc = (sub == 0) ? g_h3s[i] : 0.f;
    const int* sl = g_slot + (size_t)i * SLOT;
    for (int j = sub; j < cnt; j += 8) {
        int s = __ldg(&sl[j]);
        acc += g_h3s[s];
    }
#pragma unroll
    for (int o = 4; o; o >>= 1) acc += __shfl_xor_sync(0xffffffffu, acc, o);
    if (sub == 0) {
        g_x3[i] = fmaf(acc * di, Ws3[0], bs3[0]) * g_h3[i];
        g_cnt[i] = 0;
    }
}

// ---------------- fused sort-pool + conv head ----------------
__global__ void __launch_bounds__(128) k_head(
    const float* __restrict__ Wc1, const float* __restrict__ bc1,
    const float* __restrict__ Wc2, const float* __restrict__ bc2,
    const float* __restrict__ Wl1, const float* __restrict__ bl1,
    const float* __restrict__ Wl2, const float* __restrict__ bl2,
    float* __restrict__ out) {
    __shared__ float x3s[NPG];
    __shared__ unsigned long long keys[NPG];
    __shared__ int sel[KSEL];
    __shared__ float pooled[KSEL * DT];
    __shared__ float c1s[16 * 30];
    __shared__ float mps[16 * 15];
    __shared__ float flat[32 * 11];
    __shared__ float red[128];
    int g = blockIdx.x, tid = threadIdx.x;
    int base = g * NPG;

    for (int i = tid; i < NPG; i += 128) x3s[i] = g_x3[base + i];
    __syncthreads();
    for (int i = tid; i < NPG; i += 128) {
        unsigned u = __float_as_uint(-x3s[i]);
        u = (u & 0x80000000u) ? ~u : (u | 0x80000000u);
        keys[i] = ((unsigned long long)u << 32) | (unsigned)i;
    }
    __syncthreads();
    if (tid < NPG) {
        unsigned long long ki = keys[tid];
        int c = 0;
        for (int j = 0; j < NPG; j++) c += (keys[j] < ki) ? 1 : 0;
        if (c < KSEL) sel[c] = tid;
    }
    __syncthreads();
    for (int idx = tid; idx < KSEL * DT; idx += 128) {
        int r = idx / DT, d = idx - r * DT;
        int ln = sel[r];
        int node = base + ln;
        float v;
        if (d < 64) v = g_s1v[node] * g_h[node * 64 + d];
        else if (d < 128) v = g_s2v[node] * g_h2[node * 64 + d - 64];
        else v = x3s[ln];
        pooled[idx] = v;
    }
    __syncthreads();
    for (int idx = tid; idx < 16 * 30; idx += 128) {
        int o = idx / 30, k = idx - o * 30;
        float acc = bc1[o];
        const float* w = Wc1 + o * DT;
        for (int d = 0; d < DT; d++) acc += pooled[k * DT + d] * w[d];
        c1s[o * 30 + k] = fmaxf(acc, 0.f);
    }
    __syncthreads();
    for (int idx = tid; idx < 16 * 15; idx += 128) {
        int o = idx / 15, p = idx - o * 15;
        mps[idx] = fmaxf(c1s[o * 30 + 2 * p], c1s[o * 30 + 2 * p + 1]);
    }
    __syncthreads();
    for (int idx = tid; idx < 32 * 11; idx += 128) {
        int o = idx / 11, p = idx - o * 11;
        float acc = bc2[o];
        for (int i2 = 0; i2 < 16; i2++) {
            const float* w = Wc2 + (o * 16 + i2) * 5;
#pragma unroll
            for (int t = 0; t < 5; t++) acc += mps[i2 * 15 + p + t] * w[t];
        }
        flat[idx] = fmaxf(acc, 0.f);
    }
    __syncthreads();
    {
        int w = tid >> 5, lane = tid & 31;
        float fl[11];
#pragma unroll
        for (int it = 0; it < 11; it++) fl[it] = flat[lane + it * 32];
        for (int jj = 0; jj < 32; jj++) {
            int j = w * 32 + jj;
            const float* wr = Wl1 + j * 352;
            float acc = 0.f;
#pragma unroll
            for (int it = 0; it < 11; it++) acc += fl[it] * wr[lane + it * 32];
#pragma unroll
            for (int o = 16; o; o >>= 1) acc += __shfl_xor_sync(0xffffffffu, acc, o);
            if (lane == 0) {
                float hv = fmaxf(acc + bl1[j], 0.f);
                red[j] = hv * Wl2[j];
            }
        }
    }
    __syncthreads();
    for (int off = 64; off; off >>= 1) {
        if (tid < off) red[tid] += red[tid + off];
        __syncthreads();
    }
    if (tid == 0) out[g] = red[0] + bl2[0];
}

// ---------------- launcher ----------------
extern "C" void kernel_launch(void* const* d_in, const int* in_sizes, int n_in,
                              void* d_out, int out_size) {
    const float* x   = (const float*)d_in[0];
    const int*   ei  = (const int*)  d_in[1];
    const float* W1  = (const float*)d_in[2];
    const float* b1  = (const float*)d_in[3];
    const float* W2  = (const float*)d_in[4];
    const float* b2  = (const float*)d_in[5];
    const float* W3  = (const float*)d_in[6];
    const float* b3  = (const float*)d_in[7];
    const float* Ws1 = (const float*)d_in[8];
    const float* bs1 = (const float*)d_in[9];
    const float* Ws2 = (const float*)d_in[10];
    const float* bs2 = (const float*)d_in[11];
    const float* Ws3 = (const float*)d_in[12];
    const float* bs3 = (const float*)d_in[13];
    const float* Wc1 = (const float*)d_in[14];
    const float* bc1 = (const float*)d_in[15];
    const float* Wc2 = (const float*)d_in[16];
    const float* bc2 = (const float*)d_in[17];
    const float* Wl1 = (const float*)d_in[18];
    const float* bl1 = (const float*)d_in[19];
    const float* Wl2 = (const float*)d_in[20];
    const float* bl2 = (const float*)d_in[21];
    float* out = (float*)d_out;

    float *dH, *dh, *dh2;
    cudaGetSymbolAddress((void**)&dH,  g_H);
    cudaGetSymbolAddress((void**)&dh,  g_h);
    cudaGetSymbolAddress((void**)&dh2, g_h2);

    const int TB = 256;
    int gE  = (EDGES + TB - 1) / TB;
    int gW  = (NNODE * 32 + TB - 1) / TB;
    int gW8 = (NNODE * 8 + TB - 1) / TB;

    // 0: structure
    k_fillslots<<<gE, TB>>>(ei);
    // 1: gemm128
    k_gemm<FIN><<<(NNODE + 127) / 128, 256>>>(x, W1, dH);
    // 2: agg64f #1 -> h1, dots.x
    k_agg64f<false><<<gW, TB>>>(dH, b1, Ws1, nullptr, dh, 0);
    // 3: gemm64 (h1 -> H2)   <-- profiled slot
    k_gemm<D><<<(NNODE + 127) / 128, 256>>>(dh, W2, dH);
    // 4: agg64f #2 -> h2, dots.y, dots.z
    k_agg64f<true><<<gW, TB>>>(dH, b2, Ws2, W3, dh2, 1);
    // 5: fused scalar gates -> s1v, s2v, h3
    k_sgates<<<gW8, TB>>>(bs1, bs2, b3);
    // 6: s3/x3 (+ cnt reset)
    k_s3<<<gW8, TB>>>(Ws3, bs3);
    // 7: head
    k_head<<<NGRAPH, 128>>>(Wc1, bc1, Wc2, bc2, Wl1, bl1, Wl2, bl2, out);

    (void)in_sizes; (void)n_in; (void)out_size;
}